// round 8
// baseline (speedup 1.0000x reference)
#include <cuda_runtime.h>
#include <math.h>

// Shapes (compile-time constants from the reference)
#define T_DIM   512
#define B_DIM   32
#define TS_FD   76
#define N_WF    200
#define WF_LEN  1000
#define TEXT_D  200
#define WF_D    100
#define HID     256
#define FC_H    256
#define NCLS    2
#define ROWS    (T_DIM * B_DIM)          // 16384
#define FEAT_D  (TEXT_D + HID + WF_D)    // 556

// Scratch (no cudaMalloc allowed): ~56MB of __device__ globals
__device__ float g_C1[B_DIM * N_WF * WF_D];    // wf_out, (B*N_WF, WF_D) = (6400,100)
__device__ float g_feat[ROWS * FEAT_D];        // concatenated features (16384,556)
__device__ float g_H[ROWS * FC_H];             // relu hidden (16384,256)

enum { EPI_BIAS = 0, EPI_TANH = 1, EPI_SCALE = 2, EPI_RELU = 3 };

// ---------------------------------------------------------------------------
// Classic 128x128x8 register-tiled fp32 GEMM, 256 threads, 8x8 per thread.
// Batched via blockIdx.z strides. M must be a multiple of 128 (true for all
// call sites: 6400, 16384, 512). N and K are fully guarded.
// ---------------------------------------------------------------------------
template <int EPI>
__global__ __launch_bounds__(256) void sgemm128(
    const float* __restrict__ A, int lda, long aStride,
    const float* __restrict__ B, int ldb, long bStride,
    float*       __restrict__ C, int ldc, long cStride,
    int N, int K,
    const float* __restrict__ bias, float scale)
{
    A += (long)blockIdx.z * aStride;
    B += (long)blockIdx.z * bStride;
    C += (long)blockIdx.z * cStride;

    const int row0 = blockIdx.y * 128;
    const int col0 = blockIdx.x * 128;
    const int tid  = threadIdx.x;
    const int tr   = tid >> 4;       // 0..15 (row group)
    const int tc   = tid & 15;       // 0..15 (col group)

    __shared__ float As[8][132];     // [k][m], padded rows (528B, 16B aligned)
    __shared__ float Bs[8][132];     // [k][n]

    float acc[8][8];
#pragma unroll
    for (int i = 0; i < 8; i++)
#pragma unroll
        for (int j = 0; j < 8; j++) acc[i][j] = 0.f;

    const int ar = tid >> 1;           // 0..127 : A tile row
    const int ah = (tid & 1) * 4;      // 0 or 4 : A tile k-half
    const int bk = tid >> 5;           // 0..7   : B tile k-row
    const int bc = (tid & 31) * 4;     // 0..124 : B tile col

    for (int k0 = 0; k0 < K; k0 += 8) {
        // --- load A tile (128 rows x 8 k), transposed into As[k][m] ---
        {
            const int kb = k0 + ah;
            const float* ap = A + (long)(row0 + ar) * lda + kb;
            float4 av;
            if (kb + 3 < K) {
                av = *(const float4*)ap;
            } else {
                av.x = (kb + 0 < K) ? ap[0] : 0.f;
                av.y = (kb + 1 < K) ? ap[1] : 0.f;
                av.z = (kb + 2 < K) ? ap[2] : 0.f;
                av.w = (kb + 3 < K) ? ap[3] : 0.f;
            }
            As[ah + 0][ar] = av.x;
            As[ah + 1][ar] = av.y;
            As[ah + 2][ar] = av.z;
            As[ah + 3][ar] = av.w;
        }
        // --- load B tile (8 k x 128 cols) ---
        {
            const int kb  = k0 + bk;
            const int col = col0 + bc;
            float4 bv = make_float4(0.f, 0.f, 0.f, 0.f);
            if (kb < K) {
                const float* bp = B + (long)kb * ldb + col;
                if (col + 3 < N) {
                    bv = *(const float4*)bp;
                } else {
                    if (col + 0 < N) bv.x = bp[0];
                    if (col + 1 < N) bv.y = bp[1];
                    if (col + 2 < N) bv.z = bp[2];
                    if (col + 3 < N) bv.w = bp[3];
                }
            }
            *(float4*)&Bs[bk][bc] = bv;
        }
        __syncthreads();

#pragma unroll
        for (int kk = 0; kk < 8; kk++) {
            float4 a0 = *(const float4*)&As[kk][tr * 8];
            float4 a1 = *(const float4*)&As[kk][tr * 8 + 4];
            float4 b0 = *(const float4*)&Bs[kk][tc * 8];
            float4 b1 = *(const float4*)&Bs[kk][tc * 8 + 4];
            float a[8] = {a0.x, a0.y, a0.z, a0.w, a1.x, a1.y, a1.z, a1.w};
            float b[8] = {b0.x, b0.y, b0.z, b0.w, b1.x, b1.y, b1.z, b1.w};
#pragma unroll
            for (int i = 0; i < 8; i++)
#pragma unroll
                for (int j = 0; j < 8; j++)
                    acc[i][j] = fmaf(a[i], b[j], acc[i][j]);
        }
        __syncthreads();
    }

    // --- epilogue ---
#pragma unroll
    for (int i = 0; i < 8; i++) {
        const int r = row0 + tr * 8 + i;
#pragma unroll
        for (int j = 0; j < 8; j++) {
            const int col = col0 + tc * 8 + j;
            if (col < N) {
                float v = acc[i][j];
                if (EPI == EPI_BIAS)       v += bias[col];
                else if (EPI == EPI_TANH)  v = tanhf(v + bias[col]);
                else if (EPI == EPI_SCALE) v *= scale;
                else { v += bias[col]; v = v > 0.f ? v : 0.f; }
                C[(long)r * ldc + col] = v;
            }
        }
    }
}

// ---------------------------------------------------------------------------
// Copy texts (16384 x 200, contiguous) into feat[:, 0:200] (ldc = 556)
// ---------------------------------------------------------------------------
__global__ __launch_bounds__(256) void pack_texts_kernel(const float* __restrict__ texts)
{
    const int idx = blockIdx.x * blockDim.x + threadIdx.x; // over ROWS * 50 float4s
    if (idx >= ROWS * (TEXT_D / 4)) return;
    const int r = idx / (TEXT_D / 4);
    const int c = idx % (TEXT_D / 4);
    float4 v = *(const float4*)(texts + (long)r * TEXT_D + c * 4);
    *(float4*)(g_feat + (long)r * FEAT_D + c * 4) = v;
}

// ---------------------------------------------------------------------------
// Head: out[r, c] = sum_j H[r, j] * W2[j, c] + b2[c].  One warp per row.
// ---------------------------------------------------------------------------
__global__ __launch_bounds__(256) void head_kernel(
    const float* __restrict__ H, const float* __restrict__ W2,
    const float* __restrict__ b2, float* __restrict__ out)
{
    __shared__ float w2s[FC_H * NCLS];
    const int tid = threadIdx.x;
    for (int i = tid; i < FC_H * NCLS; i += 256) w2s[i] = W2[i];
    __syncthreads();

    const int warp = tid >> 5;
    const int lane = tid & 31;
    const int r = blockIdx.x * 8 + warp;

    const float* h = H + (long)r * FC_H + lane * 8;
    float4 v0 = *(const float4*)(h);
    float4 v1 = *(const float4*)(h + 4);
    float hv[8] = {v0.x, v0.y, v0.z, v0.w, v1.x, v1.y, v1.z, v1.w};

    float s0 = 0.f, s1 = 0.f;
#pragma unroll
    for (int i = 0; i < 8; i++) {
        const int j = lane * 8 + i;
        s0 = fmaf(hv[i], w2s[j * 2 + 0], s0);
        s1 = fmaf(hv[i], w2s[j * 2 + 1], s1);
    }
#pragma unroll
    for (int m = 16; m > 0; m >>= 1) {
        s0 += __shfl_xor_sync(0xFFFFFFFFu, s0, m);
        s1 += __shfl_xor_sync(0xFFFFFFFFu, s1, m);
    }
    if (lane == 0) {
        out[(long)r * NCLS + 0] = s0 + b2[0];
        out[(long)r * NCLS + 1] = s1 + b2[1];
    }
}

// ---------------------------------------------------------------------------
extern "C" void kernel_launch(void* const* d_in, const int* in_sizes, int n_in,
                              void* d_out, int out_size)
{
    const float* texts = (const float*)d_in[0];   // (512,32,200)
    const float* ts    = (const float*)d_in[1];   // (512,32,76)
    const float* wave  = (const float*)d_in[2];   // (32,200,1000)
    const float* wwm   = (const float*)d_in[3];   // (32,512,200)
    const float* W_wf  = (const float*)d_in[4];   // (1000,100)
    const float* b_wf  = (const float*)d_in[5];
    const float* W_ts  = (const float*)d_in[6];   // (76,256)
    const float* b_ts  = (const float*)d_in[7];
    const float* W1    = (const float*)d_in[8];   // (556,256)
    const float* b1    = (const float*)d_in[9];
    const float* W2    = (const float*)d_in[10];  // (256,2)
    const float* b2    = (const float*)d_in[11];
    float* out = (float*)d_out;

    float *C1, *feat, *H;
    cudaGetSymbolAddress((void**)&C1,   g_C1);
    cudaGetSymbolAddress((void**)&feat, g_feat);
    cudaGetSymbolAddress((void**)&H,    g_H);

    // 1) feat[:, 0:200] = texts (t-major rows, matching output rows)
    pack_texts_kernel<<<(ROWS * (TEXT_D / 4) + 255) / 256, 256>>>(texts);

    // 2) C1 = waveform @ W_wf + b_wf  : (6400 x 100 x 1000)
    sgemm128<EPI_BIAS><<<dim3(1, 50, 1), 256>>>(
        wave, WF_LEN, 0, W_wf, WF_D, 0, C1, WF_D, 0,
        WF_D, WF_LEN, b_wf, 1.f);

    // 3) feat[:, 200:456] = tanh(ts @ W_ts + b_ts) : (16384 x 256 x 76)
    sgemm128<EPI_TANH><<<dim3(2, 128, 1), 256>>>(
        ts, TS_FD, 0, W_ts, HID, 0, feat + TEXT_D, FEAT_D, 0,
        HID, TS_FD, b_ts, 1.f);

    // 4) feat[:, 456:556] = bmm(wwm, C1) / 200 : 32 x (512 x 100 x 200)
    //    feat row for batch z, local row t is z*512 + t  (B-major, as reference)
    sgemm128<EPI_SCALE><<<dim3(1, 4, 32), 256>>>(
        wwm, N_WF, (long)T_DIM * N_WF,
        C1, WF_D, (long)N_WF * WF_D,
        feat + TEXT_D + HID, FEAT_D, (long)T_DIM * FEAT_D,
        WF_D, N_WF, nullptr, 1.f / (float)N_WF);

    // 5) H = relu(feat @ W1 + b1) : (16384 x 256 x 556)
    sgemm128<EPI_RELU><<<dim3(2, 128, 1), 256>>>(
        feat, FEAT_D, 0, W1, FC_H, 0, H, FC_H, 0,
        FC_H, FEAT_D, b1, 1.f);

    // 6) out = H @ W2 + b2 : (16384 x 2 x 256)
    head_kernel<<<ROWS / 8, 256>>>(H, W2, b2, out);
}

// round 9
// speedup vs baseline: 1.4572x; 1.4572x over previous
#include <cuda_runtime.h>
#include <math.h>

// Shapes (compile-time constants from the reference)
#define T_DIM   512
#define B_DIM   32
#define TS_FD   76
#define N_WF    200
#define WF_LEN  1000
#define TEXT_D  200
#define WF_D    100
#define HID     256
#define FC_H    256
#define NCLS    2
#define ROWS    (T_DIM * B_DIM)          // 16384
#define FEAT_D  (TEXT_D + HID + WF_D)    // 556
#define C1_ELEMS (B_DIM * N_WF * WF_D)   // 640000

// Scratch (no cudaMalloc allowed): __device__ globals
__device__ float g_C1[C1_ELEMS];               // wf_out, (6400,100)
__device__ float g_P[3 * C1_ELEMS];            // split-K partials for stage 2
__device__ float g_feat[ROWS * FEAT_D];        // concatenated features (16384,556)
__device__ float g_H[ROWS * FC_H];             // relu hidden (16384,256)

enum { EPI_BIAS = 0, EPI_TANH = 1, EPI_SCALE = 2, EPI_RELU = 3 };

// ---------------------------------------------------------------------------
// 128x128x8 register-tiled fp32 GEMM, 256 threads, 8x8 per thread.
// Double-buffered smem with register-staged global prefetch: LDG for tile t+1
// is issued before the FFMA block for tile t (~2048 issue cycles) so DRAM/L2
// latency is hidden; one __syncthreads per k-tile.
// Batched via blockIdx.z strides (also used for split-K with partial outputs).
// M must be a multiple of 128 (all call sites: 6400, 16384, 512). N, K guarded.
// ---------------------------------------------------------------------------
template <int EPI>
__global__ __launch_bounds__(256, 2) void sgemm128(
    const float* __restrict__ A, int lda, long aStride,
    const float* __restrict__ B, int ldb, long bStride,
    float*       __restrict__ C, int ldc, long cStride,
    int N, int K,
    const float* __restrict__ bias, float scale)
{
    A += (long)blockIdx.z * aStride;
    B += (long)blockIdx.z * bStride;
    C += (long)blockIdx.z * cStride;

    const int row0 = blockIdx.y * 128;
    const int col0 = blockIdx.x * 128;
    const int tid  = threadIdx.x;
    const int tr   = tid >> 4;       // 0..15 (row group)
    const int tc   = tid & 15;       // 0..15 (col group)

    __shared__ float As[2][8][132];  // [buf][k][m], padded rows
    __shared__ float Bs[2][8][132];  // [buf][k][n]

    float acc[8][8];
#pragma unroll
    for (int i = 0; i < 8; i++)
#pragma unroll
        for (int j = 0; j < 8; j++) acc[i][j] = 0.f;

    const int ar = tid >> 1;           // 0..127 : A tile row
    const int ah = (tid & 1) * 4;      // 0 or 4 : A tile k-half
    const int bk = tid >> 5;           // 0..7   : B tile k-row
    const int bc = (tid & 31) * 4;     // 0..124 : B tile col

    const float* aBase = A + (long)(row0 + ar) * lda;

    // guarded global fetches into registers
    auto loadA = [&](int k0) -> float4 {
        const int kb = k0 + ah;
        const float* ap = aBase + kb;
        float4 av;
        if (kb + 3 < K) {
            av = *(const float4*)ap;
        } else {
            av.x = (kb + 0 < K) ? ap[0] : 0.f;
            av.y = (kb + 1 < K) ? ap[1] : 0.f;
            av.z = (kb + 2 < K) ? ap[2] : 0.f;
            av.w = (kb + 3 < K) ? ap[3] : 0.f;
        }
        return av;
    };
    auto loadB = [&](int k0) -> float4 {
        const int kb  = k0 + bk;
        const int col = col0 + bc;
        float4 bv = make_float4(0.f, 0.f, 0.f, 0.f);
        if (kb < K) {
            const float* bp = B + (long)kb * ldb + col;
            if (col + 3 < N) {
                bv = *(const float4*)bp;
            } else {
                if (col + 0 < N) bv.x = bp[0];
                if (col + 1 < N) bv.y = bp[1];
                if (col + 2 < N) bv.z = bp[2];
                if (col + 3 < N) bv.w = bp[3];
            }
        }
        return bv;
    };

    const int nt = (K + 7) / 8;

    // preload tile 0 into buffer 0
    float4 pa = loadA(0);
    float4 pb = loadB(0);
    As[0][ah + 0][ar] = pa.x;
    As[0][ah + 1][ar] = pa.y;
    As[0][ah + 2][ar] = pa.z;
    As[0][ah + 3][ar] = pa.w;
    *(float4*)&Bs[0][bk][bc] = pb;
    __syncthreads();

    for (int t = 0; t < nt; t++) {
        const int p = t & 1;
        const bool more = (t + 1 < nt);
        if (more) {                       // prefetch next tile (hidden by FFMAs)
            pa = loadA((t + 1) * 8);
            pb = loadB((t + 1) * 8);
        }

#pragma unroll
        for (int kk = 0; kk < 8; kk++) {
            float4 a0 = *(const float4*)&As[p][kk][tr * 8];
            float4 a1 = *(const float4*)&As[p][kk][tr * 8 + 4];
            float4 b0 = *(const float4*)&Bs[p][kk][tc * 8];
            float4 b1 = *(const float4*)&Bs[p][kk][tc * 8 + 4];
            float a[8] = {a0.x, a0.y, a0.z, a0.w, a1.x, a1.y, a1.z, a1.w};
            float b[8] = {b0.x, b0.y, b0.z, b0.w, b1.x, b1.y, b1.z, b1.w};
#pragma unroll
            for (int i = 0; i < 8; i++)
#pragma unroll
                for (int j = 0; j < 8; j++)
                    acc[i][j] = fmaf(a[i], b[j], acc[i][j]);
        }

        if (more) {                       // stage into the other buffer
            const int q = p ^ 1;
            As[q][ah + 0][ar] = pa.x;
            As[q][ah + 1][ar] = pa.y;
            As[q][ah + 2][ar] = pa.z;
            As[q][ah + 3][ar] = pa.w;
            *(float4*)&Bs[q][bk][bc] = pb;
        }
        __syncthreads();
    }

    // --- epilogue ---
#pragma unroll
    for (int i = 0; i < 8; i++) {
        const int r = row0 + tr * 8 + i;
#pragma unroll
        for (int j = 0; j < 8; j++) {
            const int col = col0 + tc * 8 + j;
            if (col < N) {
                float v = acc[i][j];
                if (EPI == EPI_BIAS)       v += bias[col];
                else if (EPI == EPI_TANH)  v = tanhf(v + bias[col]);
                else if (EPI == EPI_SCALE) v *= scale;
                else { v += bias[col]; v = v > 0.f ? v : 0.f; }
                C[(long)r * ldc + col] = v;
            }
        }
    }
}

// ---------------------------------------------------------------------------
// Reduce the 3 split-K partials of stage 2 and add bias: C1 = P0+P1+P2 + b_wf
// ---------------------------------------------------------------------------
__global__ __launch_bounds__(256) void reduce3_bias_kernel(const float* __restrict__ b_wf)
{
    const int idx = blockIdx.x * 256 + threadIdx.x;
    if (idx >= C1_ELEMS) return;
    const int c = idx % WF_D;
    g_C1[idx] = g_P[idx] + g_P[idx + C1_ELEMS] + g_P[idx + 2 * C1_ELEMS] + b_wf[c];
}

// ---------------------------------------------------------------------------
// Copy texts (16384 x 200, contiguous) into feat[:, 0:200] (ldc = 556)
// ---------------------------------------------------------------------------
__global__ __launch_bounds__(256) void pack_texts_kernel(const float* __restrict__ texts)
{
    const int idx = blockIdx.x * blockDim.x + threadIdx.x; // over ROWS * 50 float4s
    if (idx >= ROWS * (TEXT_D / 4)) return;
    const int r = idx / (TEXT_D / 4);
    const int c = idx % (TEXT_D / 4);
    float4 v = *(const float4*)(texts + (long)r * TEXT_D + c * 4);
    *(float4*)(g_feat + (long)r * FEAT_D + c * 4) = v;
}

// ---------------------------------------------------------------------------
// Head: out[r, c] = sum_j H[r, j] * W2[j, c] + b2[c].  One warp per row.
// ---------------------------------------------------------------------------
__global__ __launch_bounds__(256) void head_kernel(
    const float* __restrict__ H, const float* __restrict__ W2,
    const float* __restrict__ b2, float* __restrict__ out)
{
    __shared__ float w2s[FC_H * NCLS];
    const int tid = threadIdx.x;
    for (int i = tid; i < FC_H * NCLS; i += 256) w2s[i] = W2[i];
    __syncthreads();

    const int warp = tid >> 5;
    const int lane = tid & 31;
    const int r = blockIdx.x * 8 + warp;

    const float* h = H + (long)r * FC_H + lane * 8;
    float4 v0 = *(const float4*)(h);
    float4 v1 = *(const float4*)(h + 4);
    float hv[8] = {v0.x, v0.y, v0.z, v0.w, v1.x, v1.y, v1.z, v1.w};

    float s0 = 0.f, s1 = 0.f;
#pragma unroll
    for (int i = 0; i < 8; i++) {
        const int j = lane * 8 + i;
        s0 = fmaf(hv[i], w2s[j * 2 + 0], s0);
        s1 = fmaf(hv[i], w2s[j * 2 + 1], s1);
    }
#pragma unroll
    for (int m = 16; m > 0; m >>= 1) {
        s0 += __shfl_xor_sync(0xFFFFFFFFu, s0, m);
        s1 += __shfl_xor_sync(0xFFFFFFFFu, s1, m);
    }
    if (lane == 0) {
        out[(long)r * NCLS + 0] = s0 + b2[0];
        out[(long)r * NCLS + 1] = s1 + b2[1];
    }
}

// ---------------------------------------------------------------------------
extern "C" void kernel_launch(void* const* d_in, const int* in_sizes, int n_in,
                              void* d_out, int out_size)
{
    const float* texts = (const float*)d_in[0];   // (512,32,200)
    const float* ts    = (const float*)d_in[1];   // (512,32,76)
    const float* wave  = (const float*)d_in[2];   // (32,200,1000)
    const float* wwm   = (const float*)d_in[3];   // (32,512,200)
    const float* W_wf  = (const float*)d_in[4];   // (1000,100)
    const float* b_wf  = (const float*)d_in[5];
    const float* W_ts  = (const float*)d_in[6];   // (76,256)
    const float* b_ts  = (const float*)d_in[7];
    const float* W1    = (const float*)d_in[8];   // (556,256)
    const float* b1    = (const float*)d_in[9];
    const float* W2    = (const float*)d_in[10];  // (256,2)
    const float* b2    = (const float*)d_in[11];
    float* out = (float*)d_out;

    float *C1, *P, *feat, *H;
    cudaGetSymbolAddress((void**)&C1,   g_C1);
    cudaGetSymbolAddress((void**)&P,    g_P);
    cudaGetSymbolAddress((void**)&feat, g_feat);
    cudaGetSymbolAddress((void**)&H,    g_H);

    // 1) feat[:, 0:200] = texts (t-major rows, matching output rows)
    pack_texts_kernel<<<(ROWS * (TEXT_D / 4) + 255) / 256, 256>>>(texts);

    // 2) C1 = waveform @ W_wf + b_wf : (6400 x 100 x 1000), split-K=3 (336/336/328)
    //    z indexes the k-chunk: A shifts by 336 in k, B by 336 rows, C to partial z.
    sgemm128<EPI_SCALE><<<dim3(1, 50, 2), 256>>>(
        wave, WF_LEN, 336,
        W_wf, WF_D, (long)336 * WF_D,
        P, WF_D, (long)C1_ELEMS,
        WF_D, 336, nullptr, 1.f);
    sgemm128<EPI_SCALE><<<dim3(1, 50, 1), 256>>>(
        wave + 672, WF_LEN, 0,
        W_wf + (long)672 * WF_D, WF_D, 0,
        P + (long)2 * C1_ELEMS, WF_D, 0,
        WF_D, 328, nullptr, 1.f);
    reduce3_bias_kernel<<<(C1_ELEMS + 255) / 256, 256>>>(b_wf);

    // 3) feat[:, 200:456] = tanh(ts @ W_ts + b_ts) : (16384 x 256 x 76)
    sgemm128<EPI_TANH><<<dim3(2, 128, 1), 256>>>(
        ts, TS_FD, 0, W_ts, HID, 0, feat + TEXT_D, FEAT_D, 0,
        HID, TS_FD, b_ts, 1.f);

    // 4) feat[:, 456:556] = bmm(wwm, C1) / 200 : 32 x (512 x 100 x 200)
    sgemm128<EPI_SCALE><<<dim3(1, 4, 32), 256>>>(
        wwm, N_WF, (long)T_DIM * N_WF,
        C1, WF_D, (long)N_WF * WF_D,
        feat + TEXT_D + HID, FEAT_D, (long)T_DIM * FEAT_D,
        WF_D, N_WF, nullptr, 1.f / (float)N_WF);

    // 5) H = relu(feat @ W1 + b1) : (16384 x 256 x 556)
    sgemm128<EPI_RELU><<<dim3(2, 128, 1), 256>>>(
        feat, FEAT_D, 0, W1, FC_H, 0, H, FC_H, 0,
        FC_H, FEAT_D, b1, 1.f);

    // 6) out = H @ W2 + b2 : (16384 x 2 x 256)
    head_kernel<<<ROWS / 8, 256>>>(H, W2, b2, out);
}